// round 2
// baseline (speedup 1.0000x reference)
#include <cuda_runtime.h>
#include <math.h>

#define D_DIM   768
#define BATCH   4
#define SEQ     2048
#define M_ROWS  (BATCH * SEQ)   // 8192

// Scratch (device globals: allocation-free rule)
__device__ float g_qkv[3ULL * M_ROWS * D_DIM];                    // Q,K,V  (75 MB)
__device__ float g_scores[(unsigned long long)BATCH * SEQ * SEQ]; // scores/probs (67 MB)

// ---------------------------------------------------------------------------
// NT GEMM for QKV:  Y[m][e] = sum_d x[m][d] * W[e][d]
// 64x64 C tile, 256 threads, 4x4 per thread, K chunks of 16.
// grid = (D_DIM/64, M_ROWS/64, 3)  z selects {wq,wk,wv}
// ---------------------------------------------------------------------------
__global__ void qkv_gemm_kernel(const float* __restrict__ x,
                                const float* __restrict__ wq,
                                const float* __restrict__ wk,
                                const float* __restrict__ wv) {
    const float* W = (blockIdx.z == 0) ? wq : (blockIdx.z == 1) ? wk : wv;
    float* C = g_qkv + (size_t)blockIdx.z * M_ROWS * D_DIM;

    __shared__ float As[64][17];
    __shared__ float Bs[64][17];

    const int tid = threadIdx.x;
    const int tx = tid & 15;       // n dir
    const int ty = tid >> 4;       // m dir
    const int row0 = blockIdx.y * 64;
    const int col0 = blockIdx.x * 64;
    const int lr = tid >> 2;        // load row 0..63
    const int lc = (tid & 3) * 4;   // load col 0,4,8,12

    float c[4][4] = {};

    for (int k0 = 0; k0 < D_DIM; k0 += 16) {
        float4 a4 = *(const float4*)(x + (size_t)(row0 + lr) * D_DIM + k0 + lc);
        float4 b4 = *(const float4*)(W + (size_t)(col0 + lr) * D_DIM + k0 + lc);
        As[lr][lc + 0] = a4.x; As[lr][lc + 1] = a4.y; As[lr][lc + 2] = a4.z; As[lr][lc + 3] = a4.w;
        Bs[lr][lc + 0] = b4.x; Bs[lr][lc + 1] = b4.y; Bs[lr][lc + 2] = b4.z; Bs[lr][lc + 3] = b4.w;
        __syncthreads();
        #pragma unroll
        for (int kk = 0; kk < 16; ++kk) {
            float a[4], b[4];
            #pragma unroll
            for (int i = 0; i < 4; ++i) a[i] = As[ty * 4 + i][kk];
            #pragma unroll
            for (int j = 0; j < 4; ++j) b[j] = Bs[tx * 4 + j][kk];
            #pragma unroll
            for (int i = 0; i < 4; ++i)
                #pragma unroll
                for (int j = 0; j < 4; ++j)
                    c[i][j] = fmaf(a[i], b[j], c[i][j]);
        }
        __syncthreads();
    }

    #pragma unroll
    for (int i = 0; i < 4; ++i)
        #pragma unroll
        for (int j = 0; j < 4; ++j)
            C[(size_t)(row0 + ty * 4 + i) * D_DIM + col0 + tx * 4 + j] = c[i][j];
}

// ---------------------------------------------------------------------------
// Scores NT GEMM: S[b][q][k] = dot(Q[b,q,:], K[b,k,:])  (raw, unscaled)
// grid = (SEQ/64, SEQ/64, BATCH); causal tile skip: k-tile > q-tile -> no work
// ---------------------------------------------------------------------------
__global__ void scores_gemm_kernel() {
    if (blockIdx.x > blockIdx.y) return;   // fully-masked tile

    const int b = blockIdx.z;
    const float* Q = g_qkv + (size_t)b * SEQ * D_DIM;                       // slot 0
    const float* K = g_qkv + ((size_t)M_ROWS + (size_t)b * SEQ) * D_DIM;    // slot 1
    float* S = g_scores + (size_t)b * SEQ * SEQ;

    __shared__ float As[64][17];
    __shared__ float Bs[64][17];

    const int tid = threadIdx.x;
    const int tx = tid & 15;
    const int ty = tid >> 4;
    const int row0 = blockIdx.y * 64;   // q
    const int col0 = blockIdx.x * 64;   // k
    const int lr = tid >> 2;
    const int lc = (tid & 3) * 4;

    float c[4][4] = {};

    for (int k0 = 0; k0 < D_DIM; k0 += 16) {
        float4 a4 = *(const float4*)(Q + (size_t)(row0 + lr) * D_DIM + k0 + lc);
        float4 b4 = *(const float4*)(K + (size_t)(col0 + lr) * D_DIM + k0 + lc);
        As[lr][lc + 0] = a4.x; As[lr][lc + 1] = a4.y; As[lr][lc + 2] = a4.z; As[lr][lc + 3] = a4.w;
        Bs[lr][lc + 0] = b4.x; Bs[lr][lc + 1] = b4.y; Bs[lr][lc + 2] = b4.z; Bs[lr][lc + 3] = b4.w;
        __syncthreads();
        #pragma unroll
        for (int kk = 0; kk < 16; ++kk) {
            float a[4], b4r[4];
            #pragma unroll
            for (int i = 0; i < 4; ++i) a[i] = As[ty * 4 + i][kk];
            #pragma unroll
            for (int j = 0; j < 4; ++j) b4r[j] = Bs[tx * 4 + j][kk];
            #pragma unroll
            for (int i = 0; i < 4; ++i)
                #pragma unroll
                for (int j = 0; j < 4; ++j)
                    c[i][j] = fmaf(a[i], b4r[j], c[i][j]);
        }
        __syncthreads();
    }

    #pragma unroll
    for (int i = 0; i < 4; ++i)
        #pragma unroll
        for (int j = 0; j < 4; ++j)
            S[(size_t)(row0 + ty * 4 + i) * SEQ + col0 + tx * 4 + j] = c[i][j];
}

// ---------------------------------------------------------------------------
// Row softmax with causal mask, in place over g_scores.
// grid = BATCH*SEQ blocks, 256 threads. Single expf per element:
//   pass 1: row max; pass 2: e=exp(), store, accumulate sum; pass 3: scale + zero mask
// ---------------------------------------------------------------------------
__global__ void softmax_kernel() {
    const int r = blockIdx.x;          // 0..8191
    const int q = r & (SEQ - 1);
    float* row = g_scores + (size_t)r * SEQ;
    const float scale = rsqrtf((float)D_DIM);
    const int tid = threadIdx.x;
    const int lane = tid & 31;
    const int wid = tid >> 5;

    __shared__ float red[8];

    // ---- pass 1: max over valid entries ----
    float m = -INFINITY;
    for (int k = tid; k <= q; k += 256) m = fmaxf(m, row[k] * scale);
    #pragma unroll
    for (int s = 16; s > 0; s >>= 1) m = fmaxf(m, __shfl_xor_sync(0xffffffffu, m, s));
    if (lane == 0) red[wid] = m;
    __syncthreads();
    m = red[lane & 7];
    #pragma unroll
    for (int s = 4; s > 0; s >>= 1) m = fmaxf(m, __shfl_xor_sync(0xffffffffu, m, s));
    m = __shfl_sync(0xffffffffu, m, 0);

    // ---- pass 2: exp + store + sum ----
    float sum = 0.f;
    for (int k = tid; k <= q; k += 256) {
        float e = expf(row[k] * scale - m);
        row[k] = e;
        sum += e;
    }
    #pragma unroll
    for (int s = 16; s > 0; s >>= 1) sum += __shfl_xor_sync(0xffffffffu, sum, s);
    __syncthreads();          // red[] reuse
    if (lane == 0) red[wid] = sum;
    __syncthreads();
    sum = red[lane & 7];
    #pragma unroll
    for (int s = 4; s > 0; s >>= 1) sum += __shfl_xor_sync(0xffffffffu, sum, s);
    const float inv_sum = 1.0f / __shfl_sync(0xffffffffu, sum, 0);

    // ---- pass 3: normalize valid entries, zero masked entries ----
    for (int k = tid; k < SEQ; k += 256) {
        row[k] = (k <= q) ? row[k] * inv_sum : 0.0f;
    }
}

// ---------------------------------------------------------------------------
// NN GEMM: O[b][q][e] = sum_k P[b][q][k] * V[b][k][e]
// grid = (D_DIM/64, SEQ/64, BATCH); k-loop truncated at q-tile end (P zero past q)
// ---------------------------------------------------------------------------
__global__ void pv_gemm_kernel(float* __restrict__ out) {
    const int b = blockIdx.z;
    const float* P = g_scores + (size_t)b * SEQ * SEQ;
    const float* V = g_qkv + (2ULL * M_ROWS + (size_t)b * SEQ) * D_DIM;   // slot 2
    float* O = out + (size_t)b * SEQ * D_DIM;

    __shared__ float As[64][17];   // P tile  [q][k]
    __shared__ float Bs[16][65];   // V tile  [k][e]

    const int tid = threadIdx.x;
    const int tx = tid & 15;       // e dir
    const int ty = tid >> 4;       // q dir
    const int row0 = blockIdx.y * 64;   // q
    const int col0 = blockIdx.x * 64;   // e
    const int lra = tid >> 2;
    const int lca = (tid & 3) * 4;
    const int lrb = tid >> 4;            // 0..15 (k)
    const int lcb = (tid & 15) * 4;      // 0..60 (e)

    float c[4][4] = {};

    const int kmax = row0 + 64;   // beyond this P is all zero for this q-tile

    for (int k0 = 0; k0 < kmax; k0 += 16) {
        float4 a4 = *(const float4*)(P + (size_t)(row0 + lra) * SEQ + k0 + lca);
        float4 b4 = *(const float4*)(V + (size_t)(k0 + lrb) * D_DIM + col0 + lcb);
        As[lra][lca + 0] = a4.x; As[lra][lca + 1] = a4.y; As[lra][lca + 2] = a4.z; As[lra][lca + 3] = a4.w;
        Bs[lrb][lcb + 0] = b4.x; Bs[lrb][lcb + 1] = b4.y; Bs[lrb][lcb + 2] = b4.z; Bs[lrb][lcb + 3] = b4.w;
        __syncthreads();
        #pragma unroll
        for (int kk = 0; kk < 16; ++kk) {
            float a[4], bb[4];
            #pragma unroll
            for (int i = 0; i < 4; ++i) a[i] = As[ty * 4 + i][kk];
            #pragma unroll
            for (int j = 0; j < 4; ++j) bb[j] = Bs[kk][tx * 4 + j];
            #pragma unroll
            for (int i = 0; i < 4; ++i)
                #pragma unroll
                for (int j = 0; j < 4; ++j)
                    c[i][j] = fmaf(a[i], bb[j], c[i][j]);
        }
        __syncthreads();
    }

    #pragma unroll
    for (int i = 0; i < 4; ++i)
        #pragma unroll
        for (int j = 0; j < 4; ++j)
            O[(size_t)(row0 + ty * 4 + i) * D_DIM + col0 + tx * 4 + j] = c[i][j];
}

// ---------------------------------------------------------------------------
extern "C" void kernel_launch(void* const* d_in, const int* in_sizes, int n_in,
                              void* d_out, int out_size) {
    const float* x  = (const float*)d_in[0];
    const float* wq = (const float*)d_in[1];
    const float* wk = (const float*)d_in[2];
    const float* wv = (const float*)d_in[3];
    float* out = (float*)d_out;

    // 1) Q,K,V projections
    qkv_gemm_kernel<<<dim3(D_DIM / 64, M_ROWS / 64, 3), 256>>>(x, wq, wk, wv);
    // 2) raw scores (lower-triangular tiles only)
    scores_gemm_kernel<<<dim3(SEQ / 64, SEQ / 64, BATCH), 256>>>();
    // 3) causal softmax in place
    softmax_kernel<<<BATCH * SEQ, 256>>>();
    // 4) O = P @ V
    pv_gemm_kernel<<<dim3(D_DIM / 64, SEQ / 64, BATCH), 256>>>(out);
}

// round 3
// speedup vs baseline: 1.7583x; 1.7583x over previous
#include <cuda_runtime.h>
#include <mma.h>
#include <math.h>

using namespace nvcuda;

#define D_DIM   768
#define BATCH   4
#define SEQ     2048
#define M_ROWS  (BATCH * SEQ)   // 8192

// Scratch (device globals: allocation-free rule)
__device__ float g_qkv[3ULL * M_ROWS * D_DIM];                    // Q,K,V
__device__ float g_scores[(unsigned long long)BATCH * SEQ * SEQ]; // scores/probs

#define BM 128
#define BN 128
#define BK 32
#define LDA 40    // BK + 8 pad (multiple of 4 floats for wmma ldm)
#define LDB 40
#define LDVB 136  // BN + 8 pad for row-major V tile

// ---------------------------------------------------------------------------
// NT GEMM (tf32 wmma): C[m][n] = sum_k A[m][k] * B[n][k]
// 128x128 tile, 8 warps (2x4), warp tile 64x32 -> 4x2 wmma frags.
// Used for QKV projections and (with skip) scores.
// ---------------------------------------------------------------------------
__global__ __launch_bounds__(256) void qkv_wmma_kernel(
    const float* __restrict__ x,
    const float* __restrict__ wq,
    const float* __restrict__ wk,
    const float* __restrict__ wv) {
    const float* W = (blockIdx.z == 0) ? wq : (blockIdx.z == 1) ? wk : wv;
    float* C = g_qkv + (size_t)blockIdx.z * M_ROWS * D_DIM;

    __shared__ float As[BM * LDA];
    __shared__ float Bs[BN * LDB];

    const int tid = threadIdx.x;
    const int wid = tid >> 5;
    const int wm = wid >> 2;   // 0..1
    const int wn = wid & 3;    // 0..3
    const int row0 = blockIdx.y * BM;
    const int col0 = blockIdx.x * BN;

    wmma::fragment<wmma::accumulator, 16, 16, 8, float> c[4][2];
    #pragma unroll
    for (int i = 0; i < 4; ++i)
        #pragma unroll
        for (int j = 0; j < 2; ++j) wmma::fill_fragment(c[i][j], 0.0f);

    for (int k0 = 0; k0 < D_DIM; k0 += BK) {
        #pragma unroll
        for (int t = 0; t < 4; ++t) {
            int idx = tid + t * 256;      // float4 index 0..1023
            int r = idx >> 3;
            int c4 = (idx & 7) * 4;
            float4 a = *(const float4*)(x + (size_t)(row0 + r) * D_DIM + k0 + c4);
            *(float4*)(&As[r * LDA + c4]) = a;
            float4 b = *(const float4*)(W + (size_t)(col0 + r) * D_DIM + k0 + c4);
            *(float4*)(&Bs[r * LDB + c4]) = b;
        }
        __syncthreads();
        #pragma unroll
        for (int kk = 0; kk < BK; kk += 8) {
            wmma::fragment<wmma::matrix_a, 16, 16, 8, wmma::precision::tf32, wmma::row_major> a[4];
            wmma::fragment<wmma::matrix_b, 16, 16, 8, wmma::precision::tf32, wmma::col_major> b[2];
            #pragma unroll
            for (int i = 0; i < 4; ++i) {
                wmma::load_matrix_sync(a[i], &As[(wm * 64 + i * 16) * LDA + kk], LDA);
                #pragma unroll
                for (int e = 0; e < a[i].num_elements; ++e) a[i].x[e] = wmma::__float_to_tf32(a[i].x[e]);
            }
            #pragma unroll
            for (int j = 0; j < 2; ++j) {
                wmma::load_matrix_sync(b[j], &Bs[(wn * 32 + j * 16) * LDB + kk], LDB);
                #pragma unroll
                for (int e = 0; e < b[j].num_elements; ++e) b[j].x[e] = wmma::__float_to_tf32(b[j].x[e]);
            }
            #pragma unroll
            for (int i = 0; i < 4; ++i)
                #pragma unroll
                for (int j = 0; j < 2; ++j)
                    wmma::mma_sync(c[i][j], a[i], b[j], c[i][j]);
        }
        __syncthreads();
    }

    #pragma unroll
    for (int i = 0; i < 4; ++i)
        #pragma unroll
        for (int j = 0; j < 2; ++j)
            wmma::store_matrix_sync(&C[(size_t)(row0 + wm * 64 + i * 16) * D_DIM + col0 + wn * 32 + j * 16],
                                    c[i][j], D_DIM, wmma::mem_row_major);
}

// ---------------------------------------------------------------------------
// Scores NT GEMM (tf32 wmma): S[b][q][k] = dot(Q[b,q,:], K[b,k,:])
// grid (SEQ/128, SEQ/128, BATCH); causal tile skip.
// ---------------------------------------------------------------------------
__global__ __launch_bounds__(256) void scores_wmma_kernel() {
    if (blockIdx.x > blockIdx.y) return;   // fully-masked tile

    const int b = blockIdx.z;
    const float* Q = g_qkv + (size_t)b * SEQ * D_DIM;
    const float* K = g_qkv + ((size_t)M_ROWS + (size_t)b * SEQ) * D_DIM;
    float* S = g_scores + (size_t)b * SEQ * SEQ;

    __shared__ float As[BM * LDA];
    __shared__ float Bs[BN * LDB];

    const int tid = threadIdx.x;
    const int wid = tid >> 5;
    const int wm = wid >> 2;
    const int wn = wid & 3;
    const int row0 = blockIdx.y * BM;   // q
    const int col0 = blockIdx.x * BN;   // k

    wmma::fragment<wmma::accumulator, 16, 16, 8, float> c[4][2];
    #pragma unroll
    for (int i = 0; i < 4; ++i)
        #pragma unroll
        for (int j = 0; j < 2; ++j) wmma::fill_fragment(c[i][j], 0.0f);

    for (int k0 = 0; k0 < D_DIM; k0 += BK) {
        #pragma unroll
        for (int t = 0; t < 4; ++t) {
            int idx = tid + t * 256;
            int r = idx >> 3;
            int c4 = (idx & 7) * 4;
            float4 a = *(const float4*)(Q + (size_t)(row0 + r) * D_DIM + k0 + c4);
            *(float4*)(&As[r * LDA + c4]) = a;
            float4 bb = *(const float4*)(K + (size_t)(col0 + r) * D_DIM + k0 + c4);
            *(float4*)(&Bs[r * LDB + c4]) = bb;
        }
        __syncthreads();
        #pragma unroll
        for (int kk = 0; kk < BK; kk += 8) {
            wmma::fragment<wmma::matrix_a, 16, 16, 8, wmma::precision::tf32, wmma::row_major> a[4];
            wmma::fragment<wmma::matrix_b, 16, 16, 8, wmma::precision::tf32, wmma::col_major> b[2];
            #pragma unroll
            for (int i = 0; i < 4; ++i) {
                wmma::load_matrix_sync(a[i], &As[(wm * 64 + i * 16) * LDA + kk], LDA);
                #pragma unroll
                for (int e = 0; e < a[i].num_elements; ++e) a[i].x[e] = wmma::__float_to_tf32(a[i].x[e]);
            }
            #pragma unroll
            for (int j = 0; j < 2; ++j) {
                wmma::load_matrix_sync(b[j], &Bs[(wn * 32 + j * 16) * LDB + kk], LDB);
                #pragma unroll
                for (int e = 0; e < b[j].num_elements; ++e) b[j].x[e] = wmma::__float_to_tf32(b[j].x[e]);
            }
            #pragma unroll
            for (int i = 0; i < 4; ++i)
                #pragma unroll
                for (int j = 0; j < 2; ++j)
                    wmma::mma_sync(c[i][j], a[i], b[j], c[i][j]);
        }
        __syncthreads();
    }

    #pragma unroll
    for (int i = 0; i < 4; ++i)
        #pragma unroll
        for (int j = 0; j < 2; ++j)
            wmma::store_matrix_sync(&S[(size_t)(row0 + wm * 64 + i * 16) * SEQ + col0 + wn * 32 + j * 16],
                                    c[i][j], SEQ, wmma::mem_row_major);
}

// ---------------------------------------------------------------------------
// Row softmax with causal mask, in place. Single expf per element.
// ---------------------------------------------------------------------------
__global__ void softmax_kernel() {
    const int r = blockIdx.x;
    const int q = r & (SEQ - 1);
    float* row = g_scores + (size_t)r * SEQ;
    const float scale = rsqrtf((float)D_DIM);
    const int tid = threadIdx.x;
    const int lane = tid & 31;
    const int wid = tid >> 5;

    __shared__ float red[8];

    float m = -INFINITY;
    for (int k = tid; k <= q; k += 256) m = fmaxf(m, row[k] * scale);
    #pragma unroll
    for (int s = 16; s > 0; s >>= 1) m = fmaxf(m, __shfl_xor_sync(0xffffffffu, m, s));
    if (lane == 0) red[wid] = m;
    __syncthreads();
    m = red[lane & 7];
    #pragma unroll
    for (int s = 4; s > 0; s >>= 1) m = fmaxf(m, __shfl_xor_sync(0xffffffffu, m, s));
    m = __shfl_sync(0xffffffffu, m, 0);

    float sum = 0.f;
    for (int k = tid; k <= q; k += 256) {
        float e = expf(row[k] * scale - m);
        row[k] = e;
        sum += e;
    }
    #pragma unroll
    for (int s = 16; s > 0; s >>= 1) sum += __shfl_xor_sync(0xffffffffu, sum, s);
    __syncthreads();
    if (lane == 0) red[wid] = sum;
    __syncthreads();
    sum = red[lane & 7];
    #pragma unroll
    for (int s = 4; s > 0; s >>= 1) sum += __shfl_xor_sync(0xffffffffu, sum, s);
    const float inv_sum = 1.0f / __shfl_sync(0xffffffffu, sum, 0);

    for (int k = tid; k < SEQ; k += 256) {
        row[k] = (k <= q) ? row[k] * inv_sum : 0.0f;
    }
}

// ---------------------------------------------------------------------------
// NN GEMM (tf32 wmma): O[b][q][e] = sum_k P[b][q][k] * V[b][k][e]
// grid (D_DIM/128, SEQ/128, BATCH); k loop truncated at q-tile end.
// ---------------------------------------------------------------------------
__global__ __launch_bounds__(256) void pv_wmma_kernel(float* __restrict__ out) {
    const int b = blockIdx.z;
    const float* P = g_scores + (size_t)b * SEQ * SEQ;
    const float* V = g_qkv + (2ULL * M_ROWS + (size_t)b * SEQ) * D_DIM;
    float* O = out + (size_t)b * SEQ * D_DIM;

    __shared__ float As[BM * LDA];        // P tile [q][k]
    __shared__ float Vs[BK * LDVB];       // V tile [k][e]

    const int tid = threadIdx.x;
    const int wid = tid >> 5;
    const int wm = wid >> 2;
    const int wn = wid & 3;
    const int row0 = blockIdx.y * BM;     // q
    const int col0 = blockIdx.x * BN;     // e

    wmma::fragment<wmma::accumulator, 16, 16, 8, float> c[4][2];
    #pragma unroll
    for (int i = 0; i < 4; ++i)
        #pragma unroll
        for (int j = 0; j < 2; ++j) wmma::fill_fragment(c[i][j], 0.0f);

    const int kmax = row0 + BM;   // P is zero beyond this for the q-tile

    for (int k0 = 0; k0 < kmax; k0 += BK) {
        #pragma unroll
        for (int t = 0; t < 4; ++t) {
            int idx = tid + t * 256;
            // A (P) tile: 128 rows x 8 float4
            int ra = idx >> 3;
            int ca = (idx & 7) * 4;
            float4 a = *(const float4*)(P + (size_t)(row0 + ra) * SEQ + k0 + ca);
            *(float4*)(&As[ra * LDA + ca]) = a;
            // V tile: 32 rows x 32 float4
            int rv = idx >> 5;
            int cv = (idx & 31) * 4;
            float4 v = *(const float4*)(V + (size_t)(k0 + rv) * D_DIM + col0 + cv);
            *(float4*)(&Vs[rv * LDVB + cv]) = v;
        }
        __syncthreads();
        #pragma unroll
        for (int kk = 0; kk < BK; kk += 8) {
            wmma::fragment<wmma::matrix_a, 16, 16, 8, wmma::precision::tf32, wmma::row_major> a[4];
            wmma::fragment<wmma::matrix_b, 16, 16, 8, wmma::precision::tf32, wmma::row_major> b[2];
            #pragma unroll
            for (int i = 0; i < 4; ++i) {
                wmma::load_matrix_sync(a[i], &As[(wm * 64 + i * 16) * LDA + kk], LDA);
                #pragma unroll
                for (int e = 0; e < a[i].num_elements; ++e) a[i].x[e] = wmma::__float_to_tf32(a[i].x[e]);
            }
            #pragma unroll
            for (int j = 0; j < 2; ++j) {
                wmma::load_matrix_sync(b[j], &Vs[kk * LDVB + wn * 32 + j * 16], LDVB);
                #pragma unroll
                for (int e = 0; e < b[j].num_elements; ++e) b[j].x[e] = wmma::__float_to_tf32(b[j].x[e]);
            }
            #pragma unroll
            for (int i = 0; i < 4; ++i)
                #pragma unroll
                for (int j = 0; j < 2; ++j)
                    wmma::mma_sync(c[i][j], a[i], b[j], c[i][j]);
        }
        __syncthreads();
    }

    #pragma unroll
    for (int i = 0; i < 4; ++i)
        #pragma unroll
        for (int j = 0; j < 2; ++j)
            wmma::store_matrix_sync(&O[(size_t)(row0 + wm * 64 + i * 16) * D_DIM + col0 + wn * 32 + j * 16],
                                    c[i][j], D_DIM, wmma::mem_row_major);
}

// ---------------------------------------------------------------------------
extern "C" void kernel_launch(void* const* d_in, const int* in_sizes, int n_in,
                              void* d_out, int out_size) {
    const float* x  = (const float*)d_in[0];
    const float* wq = (const float*)d_in[1];
    const float* wk = (const float*)d_in[2];
    const float* wv = (const float*)d_in[3];
    float* out = (float*)d_out;

    qkv_wmma_kernel<<<dim3(D_DIM / BN, M_ROWS / BM, 3), 256>>>(x, wq, wk, wv);
    scores_wmma_kernel<<<dim3(SEQ / BN, SEQ / BM, BATCH), 256>>>();
    softmax_kernel<<<BATCH * SEQ, 256>>>();
    pv_wmma_kernel<<<dim3(D_DIM / BN, SEQ / BM, BATCH), 256>>>(out);
}

// round 6
// speedup vs baseline: 1.8973x; 1.0791x over previous
#include <cuda_runtime.h>
#include <mma.h>
#include <math.h>
#include <cstdint>

using namespace nvcuda;

#define D_DIM   768
#define BATCH   4
#define SEQ     2048
#define M_ROWS  (BATCH * SEQ)   // 8192

__device__ float g_qkv[3ULL * M_ROWS * D_DIM];
__device__ float g_scores[(unsigned long long)BATCH * SEQ * SEQ];

#define BM 128
#define BN 128
#define BK 16
#define LDA 20     // floats; 80B row stride, 16B-aligned
#define LDVB 136   // floats; 544B row stride, 16B-aligned

// cp.async helpers
__device__ __forceinline__ void cp16(void* smem_dst, const void* gmem_src) {
    unsigned int d = (unsigned int)__cvta_generic_to_shared(smem_dst);
    asm volatile("cp.async.cg.shared.global [%0], [%1], 16;\n" :: "r"(d), "l"(gmem_src));
}
__device__ __forceinline__ void cp_commit() {
    asm volatile("cp.async.commit_group;\n");
}
template <int N>
__device__ __forceinline__ void cp_wait() {
    asm volatile("cp.async.wait_group %0;\n" :: "n"(N));
}

// ---------------------------------------------------------------------------
// NT GEMM (tf32 wmma, cp.async double-buffered):
//   C[m][n] = sum_k A[m][k] * B[n][k], A row-major [.,D], B row-major [.,D]
// 128x128 tile, 8 warps (2x4), warp tile 64x32.
// ---------------------------------------------------------------------------
struct NTShared {
    float As[2][BM * LDA];
    float Bs[2][BN * LDA];
};

__device__ __forceinline__ void nt_fill(NTShared* s, int buf,
                                        const float* __restrict__ A,
                                        const float* __restrict__ B,
                                        int row0, int col0, int k0, int tid) {
    // 512 16B-chunks per matrix; 2 per thread per matrix
    #pragma unroll
    for (int t = 0; t < 2; ++t) {
        int c = tid + t * 256;
        int r = c >> 2;
        int cc = (c & 3) * 4;
        cp16(&s->As[buf][r * LDA + cc], A + (size_t)(row0 + r) * D_DIM + k0 + cc);
        cp16(&s->Bs[buf][r * LDA + cc], B + (size_t)(col0 + r) * D_DIM + k0 + cc);
    }
}

__device__ __forceinline__ void nt_gemm_body(const float* __restrict__ A,
                                             const float* __restrict__ B,
                                             float* __restrict__ C, int ldc,
                                             int row0, int col0) {
    __shared__ NTShared s;
    const int tid = threadIdx.x;
    const int wid = tid >> 5;
    const int wm = wid >> 2;
    const int wn = wid & 3;

    wmma::fragment<wmma::accumulator, 16, 16, 8, float> c[4][2];
    #pragma unroll
    for (int i = 0; i < 4; ++i)
        #pragma unroll
        for (int j = 0; j < 2; ++j) wmma::fill_fragment(c[i][j], 0.0f);

    const int nt = D_DIM / BK;   // 48
    nt_fill(&s, 0, A, B, row0, col0, 0, tid);
    cp_commit();

    for (int i = 0; i < nt; ++i) {
        if (i + 1 < nt) {
            nt_fill(&s, (i + 1) & 1, A, B, row0, col0, (i + 1) * BK, tid);
            cp_commit();
            cp_wait<1>();
        } else {
            cp_wait<0>();
        }
        __syncthreads();
        const int buf = i & 1;
        #pragma unroll
        for (int kk = 0; kk < BK; kk += 8) {
            wmma::fragment<wmma::matrix_a, 16, 16, 8, wmma::precision::tf32, wmma::row_major> a[4];
            wmma::fragment<wmma::matrix_b, 16, 16, 8, wmma::precision::tf32, wmma::col_major> b[2];
            #pragma unroll
            for (int ii = 0; ii < 4; ++ii) {
                wmma::load_matrix_sync(a[ii], &s.As[buf][(wm * 64 + ii * 16) * LDA + kk], LDA);
                #pragma unroll
                for (int e = 0; e < a[ii].num_elements; ++e) a[ii].x[e] = wmma::__float_to_tf32(a[ii].x[e]);
            }
            #pragma unroll
            for (int j = 0; j < 2; ++j) {
                wmma::load_matrix_sync(b[j], &s.Bs[buf][(wn * 32 + j * 16) * LDA + kk], LDA);
                #pragma unroll
                for (int e = 0; e < b[j].num_elements; ++e) b[j].x[e] = wmma::__float_to_tf32(b[j].x[e]);
            }
            #pragma unroll
            for (int ii = 0; ii < 4; ++ii)
                #pragma unroll
                for (int j = 0; j < 2; ++j)
                    wmma::mma_sync(c[ii][j], a[ii], b[j], c[ii][j]);
        }
        __syncthreads();
    }

    #pragma unroll
    for (int i = 0; i < 4; ++i)
        #pragma unroll
        for (int j = 0; j < 2; ++j)
            wmma::store_matrix_sync(&C[(size_t)(row0 + wm * 64 + i * 16) * ldc + col0 + wn * 32 + j * 16],
                                    c[i][j], ldc, wmma::mem_row_major);
}

__global__ __launch_bounds__(256) void qkv_wmma_kernel(
    const float* __restrict__ x,
    const float* __restrict__ wq,
    const float* __restrict__ wk,
    const float* __restrict__ wv) {
    const float* W = (blockIdx.z == 0) ? wq : (blockIdx.z == 1) ? wk : wv;
    float* C = g_qkv + (size_t)blockIdx.z * M_ROWS * D_DIM;
    nt_gemm_body(x, W, C, D_DIM, blockIdx.y * BM, blockIdx.x * BN);
}

__global__ __launch_bounds__(256) void scores_wmma_kernel() {
    if (blockIdx.x > blockIdx.y) return;   // fully-masked tile
    const int b = blockIdx.z;
    const float* Q = g_qkv + (size_t)b * SEQ * D_DIM;
    const float* K = g_qkv + ((size_t)M_ROWS + (size_t)b * SEQ) * D_DIM;
    float* S = g_scores + (size_t)b * SEQ * SEQ;
    nt_gemm_body(Q, K, S, SEQ, blockIdx.y * BM, blockIdx.x * BN);
}

// ---------------------------------------------------------------------------
// Row softmax with causal mask, in place. Single expf per element.
// ---------------------------------------------------------------------------
__global__ void softmax_kernel() {
    const int r = blockIdx.x;
    const int q = r & (SEQ - 1);
    float* row = g_scores + (size_t)r * SEQ;
    const float scale = rsqrtf((float)D_DIM);
    const int tid = threadIdx.x;
    const int lane = tid & 31;
    const int wid = tid >> 5;

    __shared__ float red[8];

    float m = -INFINITY;
    for (int k = tid; k <= q; k += 256) m = fmaxf(m, row[k] * scale);
    #pragma unroll
    for (int s = 16; s > 0; s >>= 1) m = fmaxf(m, __shfl_xor_sync(0xffffffffu, m, s));
    if (lane == 0) red[wid] = m;
    __syncthreads();
    m = red[lane & 7];
    #pragma unroll
    for (int s = 4; s > 0; s >>= 1) m = fmaxf(m, __shfl_xor_sync(0xffffffffu, m, s));
    m = __shfl_sync(0xffffffffu, m, 0);

    float sum = 0.f;
    for (int k = tid; k <= q; k += 256) {
        float e = expf(row[k] * scale - m);
        row[k] = e;
        sum += e;
    }
    #pragma unroll
    for (int s = 16; s > 0; s >>= 1) sum += __shfl_xor_sync(0xffffffffu, sum, s);
    __syncthreads();
    if (lane == 0) red[wid] = sum;
    __syncthreads();
    sum = red[lane & 7];
    #pragma unroll
    for (int s = 4; s > 0; s >>= 1) sum += __shfl_xor_sync(0xffffffffu, sum, s);
    const float inv_sum = 1.0f / __shfl_sync(0xffffffffu, sum, 0);

    for (int k = tid; k < SEQ; k += 256) {
        row[k] = (k <= q) ? row[k] * inv_sum : 0.0f;
    }
}

// ---------------------------------------------------------------------------
// NN GEMM (tf32 wmma, cp.async double-buffered):
//   O[b][q][e] = sum_k P[b][q][k] * V[b][k][e]; k truncated at q-tile end
// ---------------------------------------------------------------------------
struct PVShared {
    float As[2][BM * LDA];    // P tile [q][k]
    float Vs[2][BK * LDVB];   // V tile [k][e]
};

__device__ __forceinline__ void pv_fill(PVShared* s, int buf,
                                        const float* __restrict__ P,
                                        const float* __restrict__ V,
                                        int row0, int col0, int k0, int tid) {
    #pragma unroll
    for (int t = 0; t < 2; ++t) {
        int c = tid + t * 256;
        // P: 128 rows x 4 chunks
        int ra = c >> 2;
        int ca = (c & 3) * 4;
        cp16(&s->As[buf][ra * LDA + ca], P + (size_t)(row0 + ra) * SEQ + k0 + ca);
        // V: 16 rows x 32 chunks
        int rv = c >> 5;
        int cv = (c & 31) * 4;
        cp16(&s->Vs[buf][rv * LDVB + cv], V + (size_t)(k0 + rv) * D_DIM + col0 + cv);
    }
}

__global__ __launch_bounds__(256) void pv_wmma_kernel(float* __restrict__ out) {
    const int b = blockIdx.z;
    const float* P = g_scores + (size_t)b * SEQ * SEQ;
    const float* V = g_qkv + (2ULL * M_ROWS + (size_t)b * SEQ) * D_DIM;
    float* O = out + (size_t)b * SEQ * D_DIM;

    __shared__ PVShared s;
    const int tid = threadIdx.x;
    const int wid = tid >> 5;
    const int wm = wid >> 2;
    const int wn = wid & 3;
    const int row0 = blockIdx.y * BM;
    const int col0 = blockIdx.x * BN;

    wmma::fragment<wmma::accumulator, 16, 16, 8, float> c[4][2];
    #pragma unroll
    for (int i = 0; i < 4; ++i)
        #pragma unroll
        for (int j = 0; j < 2; ++j) wmma::fill_fragment(c[i][j], 0.0f);

    const int nt = (row0 + BM) / BK;   // truncate: P zero past q-tile
    pv_fill(&s, 0, P, V, row0, col0, 0, tid);
    cp_commit();

    for (int i = 0; i < nt; ++i) {
        if (i + 1 < nt) {
            pv_fill(&s, (i + 1) & 1, P, V, row0, col0, (i + 1) * BK, tid);
            cp_commit();
            cp_wait<1>();
        } else {
            cp_wait<0>();
        }
        __syncthreads();
        const int buf = i & 1;
        #pragma unroll
        for (int kk = 0; kk < BK; kk += 8) {
            wmma::fragment<wmma::matrix_a, 16, 16, 8, wmma::precision::tf32, wmma::row_major> a[4];
            wmma::fragment<wmma::matrix_b, 16, 16, 8, wmma::precision::tf32, wmma::row_major> bfr[2];
            #pragma unroll
            for (int ii = 0; ii < 4; ++ii) {
                wmma::load_matrix_sync(a[ii], &s.As[buf][(wm * 64 + ii * 16) * LDA + kk], LDA);
                #pragma unroll
                for (int e = 0; e < a[ii].num_elements; ++e) a[ii].x[e] = wmma::__float_to_tf32(a[ii].x[e]);
            }
            #pragma unroll
            for (int j = 0; j < 2; ++j) {
                wmma::load_matrix_sync(bfr[j], &s.Vs[buf][kk * LDVB + wn * 32 + j * 16], LDVB);
                #pragma unroll
                for (int e = 0; e < bfr[j].num_elements; ++e) bfr[j].x[e] = wmma::__float_to_tf32(bfr[j].x[e]);
            }
            #pragma unroll
            for (int ii = 0; ii < 4; ++ii)
                #pragma unroll
                for (int j = 0; j < 2; ++j)
                    wmma::mma_sync(c[ii][j], a[ii], bfr[j], c[ii][j]);
        }
        __syncthreads();
    }

    #pragma unroll
    for (int i = 0; i < 4; ++i)
        #pragma unroll
        for (int j = 0; j < 2; ++j)
            wmma::store_matrix_sync(&O[(size_t)(row0 + wm * 64 + i * 16) * D_DIM + col0 + wn * 32 + j * 16],
                                    c[i][j], D_DIM, wmma::mem_row_major);
}

// ---------------------------------------------------------------------------
extern "C" void kernel_launch(void* const* d_in, const int* in_sizes, int n_in,
                              void* d_out, int out_size) {
    const float* x  = (const float*)d_in[0];
    const float* wq = (const float*)d_in[1];
    const float* wk = (const float*)d_in[2];
    const float* wv = (const float*)d_in[3];
    float* out = (float*)d_out;

    qkv_wmma_kernel<<<dim3(D_DIM / BN, M_ROWS / BM, 3), 256>>>(x, wq, wk, wv);
    scores_wmma_kernel<<<dim3(SEQ / BN, SEQ / BM, BATCH), 256>>>();
    softmax_kernel<<<BATCH * SEQ, 256>>>();
    pv_wmma_kernel<<<dim3(D_DIM / BN, SEQ / BM, BATCH), 256>>>(out);
}